// round 1
// baseline (speedup 1.0000x reference)
#include <cuda_runtime.h>
#include <math.h>

#define Bc 4
#define Sc 2048
#define HDc 1024
#define Hc 16
#define Dc 64
#define Mc (Bc * Sc)          // 8192 rows
#define NQKV (3 * HDc)        // 3072

// Scratch (allocation-free rule: __device__ globals)
__device__ float g_qkv[(size_t)Mc * NQKV];   // [B,S,3,H,D] flattened = [8192, 3072]
__device__ float g_att[(size_t)Mc * HDc];    // attention output [B,S,Hd]

// ---------------------------------------------------------------------------
// Generic fp32 GEMM: C[M,N] = A[M,K] @ W[K,N], all row-major.
// 128x128 block tile, BK=16, 256 threads, 8x8 microtile.
// M,N,K all divisible by tile dims for our shapes -> no bounds checks.
// ---------------------------------------------------------------------------
__global__ __launch_bounds__(256) void gemm_kernel(
    const float* __restrict__ A, const float* __restrict__ W,
    float* __restrict__ C, int N, int K)
{
    __shared__ float As[16][128];   // [k][m] (transposed A tile)
    __shared__ float Ws[16][128];   // [k][n]

    const int tid  = threadIdx.x;
    const int row0 = blockIdx.y * 128;
    const int col0 = blockIdx.x * 128;
    const int tr   = (tid >> 4) << 3;   // 0..120
    const int tc   = (tid & 15) << 3;

    const int a_row = tid >> 1;         // 0..127
    const int a_col = (tid & 1) << 3;   // 0 or 8
    const int w_row = tid >> 4;         // 0..15
    const int w_c4  = (tid & 15) << 2;  // 0..60

    float acc[8][8];
#pragma unroll
    for (int i = 0; i < 8; i++)
#pragma unroll
        for (int j = 0; j < 8; j++) acc[i][j] = 0.f;

    for (int k0 = 0; k0 < K; k0 += 16) {
        const float* Ap = A + (size_t)(row0 + a_row) * K + k0 + a_col;
        float4 av0 = *(const float4*)Ap;
        float4 av1 = *(const float4*)(Ap + 4);
        As[a_col + 0][a_row] = av0.x;
        As[a_col + 1][a_row] = av0.y;
        As[a_col + 2][a_row] = av0.z;
        As[a_col + 3][a_row] = av0.w;
        As[a_col + 4][a_row] = av1.x;
        As[a_col + 5][a_row] = av1.y;
        As[a_col + 6][a_row] = av1.z;
        As[a_col + 7][a_row] = av1.w;

        const float* Wp = W + (size_t)(k0 + w_row) * N + col0;
        *(float4*)&Ws[w_row][w_c4]      = *(const float4*)(Wp + w_c4);
        *(float4*)&Ws[w_row][w_c4 + 64] = *(const float4*)(Wp + w_c4 + 64);
        __syncthreads();

#pragma unroll
        for (int kk = 0; kk < 16; kk++) {
            float a[8], b[8];
            *(float4*)&a[0] = *(const float4*)&As[kk][tr];
            *(float4*)&a[4] = *(const float4*)&As[kk][tr + 4];
            *(float4*)&b[0] = *(const float4*)&Ws[kk][tc];
            *(float4*)&b[4] = *(const float4*)&Ws[kk][tc + 4];
#pragma unroll
            for (int i = 0; i < 8; i++)
#pragma unroll
                for (int j = 0; j < 8; j++)
                    acc[i][j] = fmaf(a[i], b[j], acc[i][j]);
        }
        __syncthreads();
    }

#pragma unroll
    for (int i = 0; i < 8; i++) {
        float* Cp = C + (size_t)(row0 + tr + i) * N + col0 + tc;
        *(float4*)Cp       = make_float4(acc[i][0], acc[i][1], acc[i][2], acc[i][3]);
        *(float4*)(Cp + 4) = make_float4(acc[i][4], acc[i][5], acc[i][6], acc[i][7]);
    }
}

// ---------------------------------------------------------------------------
// RoPE applied in-place to the q and k slices of g_qkv ([B,S,3,H,D]).
// One thread per rotation pair. Frequencies computed in double so our
// angle error is far below the reference's own fp32 error budget.
// ---------------------------------------------------------------------------
__global__ __launch_bounds__(256) void rope_kernel(float* __restrict__ qkv)
{
    const size_t idx = (size_t)blockIdx.x * blockDim.x + threadIdx.x;
    // total = B*S*2*H*(D/2) = 8388608
    const int i    = (int)(idx & 31);               // freq index 0..31
    const int h    = (int)((idx >> 5) & 15);        // head
    const int part = (int)((idx >> 9) & 1);         // 0=q, 1=k
    const int s    = (int)((idx >> 10) & 2047);     // seq pos
    const int b    = (int)(idx >> 21);              // batch

    const double inv_freq = pow(10000.0, -2.0 * (double)i / 64.0);
    const float ang = (float)((double)s * inv_freq);
    float sn, cs;
    sincosf(ang, &sn, &cs);

    const size_t base = ((size_t)(b * Sc + s) * 3 + part) * (size_t)HDc + h * Dc;
    const float t1 = qkv[base + i];
    const float t2 = qkv[base + i + 32];
    qkv[base + i]      = t1 * cs - t2 * sn;
    qkv[base + i + 32] = t2 * cs + t1 * sn;
}

// ---------------------------------------------------------------------------
// Flash attention, fp32. One block = one (b,h) x 64-query tile.
// 256 threads as 16x16, 4x4 microtiles for both score and PV GEMMs.
// SMEM tiles use 4-float-group XOR swizzle: phys_group = grp ^ ((row>>2)&15)
// to keep transposed stores ~2-way-conflicted while reads stay float4.
// Dynamic SMEM: 4 * 64*64*4B = 64 KB.
// ---------------------------------------------------------------------------
#define SWZ(row, grp) ((((grp) ^ ((row) >> 2)) & 15) << 2)

__global__ __launch_bounds__(256) void attn_kernel(
    const float* __restrict__ qkv, float* __restrict__ o_out)
{
    extern __shared__ float sm[];
    float* Qs = sm;                 // [d][q]   swizzled, 64x64
    float* Ks = sm + 64 * 64;       // [d][k]   swizzled
    float* Vs = sm + 2 * 64 * 64;   // [k][d]   natural
    float* Ps = sm + 3 * 64 * 64;   // [k][q]   swizzled

    const int tid = threadIdx.x;
    const int bh  = blockIdx.y;
    const int b   = bh >> 4;
    const int h   = bh & 15;
    const int q0  = blockIdx.x * 64;
    const int tq  = tid >> 4;       // 0..15
    const int tk  = tid & 15;       // 0..15

    const size_t rs = (size_t)NQKV; // row stride between seq positions
    const float* qbase = qkv + (size_t)(b * Sc) * rs + h * Dc;
    const float* kbase = qbase + HDc;
    const float* vbase = qbase + 2 * HDc;

    // Load Q tile (transposed + swizzled). Each thread: 4 x float4.
#pragma unroll
    for (int it = 0; it < 4; it++) {
        int idx = tid + it * 256;       // float4 index
        int qi  = idx >> 4;             // 0..63
        int d4  = (idx & 15) << 2;      // 0..60
        float4 v = *(const float4*)(qbase + (size_t)(q0 + qi) * rs + d4);
        int grp = qi >> 2, w = qi & 3;
        Qs[(d4 + 0) * 64 + SWZ(d4 + 0, grp) + w] = v.x;
        Qs[(d4 + 1) * 64 + SWZ(d4 + 1, grp) + w] = v.y;
        Qs[(d4 + 2) * 64 + SWZ(d4 + 2, grp) + w] = v.z;
        Qs[(d4 + 3) * 64 + SWZ(d4 + 3, grp) + w] = v.w;
    }

    float acc_o[4][4];
    float m_i[4], l_i[4];
#pragma unroll
    for (int i = 0; i < 4; i++) {
        m_i[i] = -1e30f;
        l_i[i] = 0.f;
#pragma unroll
        for (int j = 0; j < 4; j++) acc_o[i][j] = 0.f;
    }

    for (int kt = 0; kt < Sc / 64; kt++) {
        __syncthreads();   // previous PV done before overwriting K/V
        const int k0 = kt * 64;
#pragma unroll
        for (int it = 0; it < 4; it++) {
            int idx = tid + it * 256;
            int ki  = idx >> 4;
            int d4  = (idx & 15) << 2;
            const float* kp = kbase + (size_t)(k0 + ki) * rs + d4;
            float4 kv = *(const float4*)kp;
            int grp = ki >> 2, w = ki & 3;
            Ks[(d4 + 0) * 64 + SWZ(d4 + 0, grp) + w] = kv.x;
            Ks[(d4 + 1) * 64 + SWZ(d4 + 1, grp) + w] = kv.y;
            Ks[(d4 + 2) * 64 + SWZ(d4 + 2, grp) + w] = kv.z;
            Ks[(d4 + 3) * 64 + SWZ(d4 + 3, grp) + w] = kv.w;
            float4 vv = *(const float4*)(vbase + (size_t)(k0 + ki) * rs + d4);
            *(float4*)&Vs[ki * 64 + d4] = vv;
        }
        __syncthreads();

        // S = Q @ K^T  (64x64, over d)
        float acc_s[4][4];
#pragma unroll
        for (int i = 0; i < 4; i++)
#pragma unroll
            for (int j = 0; j < 4; j++) acc_s[i][j] = 0.f;

#pragma unroll 8
        for (int d = 0; d < 64; d++) {
            float a[4], bb[4];
            *(float4*)a  = *(const float4*)&Qs[d * 64 + SWZ(d, tq)];
            *(float4*)bb = *(const float4*)&Ks[d * 64 + SWZ(d, tk)];
#pragma unroll
            for (int i = 0; i < 4; i++)
#pragma unroll
                for (int j = 0; j < 4; j++)
                    acc_s[i][j] = fmaf(a[i], bb[j], acc_s[i][j]);
        }

        // Online softmax. Row qi=tq*4+i lives on a contiguous 16-lane half-warp.
#pragma unroll
        for (int i = 0; i < 4; i++) {
            float mx = -1e30f;
#pragma unroll
            for (int j = 0; j < 4; j++) {
                acc_s[i][j] *= 0.125f;   // 1/sqrt(64)
                mx = fmaxf(mx, acc_s[i][j]);
            }
#pragma unroll
            for (int off = 8; off; off >>= 1)
                mx = fmaxf(mx, __shfl_xor_sync(0xFFFFFFFFu, mx, off));
            const float m_new = fmaxf(m_i[i], mx);
            const float f = expf(m_i[i] - m_new);
            float sum = 0.f;
#pragma unroll
            for (int j = 0; j < 4; j++) {
                float p = expf(acc_s[i][j] - m_new);
                // store transposed: row = tk*4+j, logical col group = tq
                Ps[(tk * 4 + j) * 64 + ((tq ^ tk) << 2) + i] = p;
                sum += p;
            }
#pragma unroll
            for (int off = 8; off; off >>= 1)
                sum += __shfl_xor_sync(0xFFFFFFFFu, sum, off);
            l_i[i] = l_i[i] * f + sum;
            m_i[i] = m_new;
#pragma unroll
            for (int j = 0; j < 4; j++) acc_o[i][j] *= f;
        }
        __syncthreads();

        // O += P @ V  (rows qi = tq*4+i, cols d = tk*4+j)
#pragma unroll 8
        for (int ki = 0; ki < 64; ki++) {
            float a[4], bb[4];
            *(float4*)a  = *(const float4*)&Ps[ki * 64 + SWZ(ki, tq)];
            *(float4*)bb = *(const float4*)&Vs[ki * 64 + tk * 4];
#pragma unroll
            for (int i = 0; i < 4; i++)
#pragma unroll
                for (int j = 0; j < 4; j++)
                    acc_o[i][j] = fmaf(a[i], bb[j], acc_o[i][j]);
        }
    }

    // Normalize and write: o[b, q0+qi, h*64 + d]
#pragma unroll
    for (int i = 0; i < 4; i++) {
        const float inv = 1.f / l_i[i];
        float4 v = make_float4(acc_o[i][0] * inv, acc_o[i][1] * inv,
                               acc_o[i][2] * inv, acc_o[i][3] * inv);
        *(float4*)(o_out + (size_t)(b * Sc + q0 + tq * 4 + i) * HDc + h * Dc + tk * 4) = v;
    }
}

// ---------------------------------------------------------------------------
extern "C" void kernel_launch(void* const* d_in, const int* in_sizes, int n_in,
                              void* d_out, int out_size)
{
    const float* x    = (const float*)d_in[0];
    const float* wqkv = (const float*)d_in[1];
    const float* wo   = (const float*)d_in[2];
    float* out = (float*)d_out;

    float* qkv = nullptr;
    float* att = nullptr;
    cudaGetSymbolAddress((void**)&qkv, g_qkv);
    cudaGetSymbolAddress((void**)&att, g_att);

    // 1) qkv = x @ wqkv : [8192,1024] x [1024,3072]
    {
        dim3 grid(NQKV / 128, Mc / 128);
        gemm_kernel<<<grid, 256>>>(x, wqkv, qkv, NQKV, HDc);
    }

    // 2) RoPE in-place on q,k slices
    {
        const size_t total = (size_t)Bc * Sc * 2 * Hc * (Dc / 2);  // 8388608
        rope_kernel<<<(unsigned)(total / 256), 256>>>(qkv);
    }

    // 3) flash attention -> g_att [B,S,Hd]
    {
        const int smem = 4 * 64 * 64 * (int)sizeof(float);  // 65536
        cudaFuncSetAttribute(attn_kernel,
                             cudaFuncAttributeMaxDynamicSharedMemorySize, smem);
        dim3 grid(Sc / 64, Bc * Hc);
        attn_kernel<<<grid, 256, smem>>>(qkv, att);
    }

    // 4) out = att @ wo : [8192,1024] x [1024,1024]
    {
        dim3 grid(HDc / 128, Mc / 128);
        gemm_kernel<<<grid, 256>>>(att, wo, out, HDc, HDc);
    }
}

// round 3
// speedup vs baseline: 1.3351x; 1.3351x over previous
#include <cuda_runtime.h>
#include <cuda_bf16.h>
#include <math.h>
#include <stdint.h>

#define Bc 4
#define Sc 2048
#define HDc 1024
#define Hc 16
#define Dc 64
#define Mc (Bc * Sc)          // 8192 rows
#define NQKV (3 * HDc)        // 3072
#define Kg 1024               // K dim of both GEMMs

// ---------------- scratch (__device__ globals; no allocs allowed) ----------
__device__ float g_qkv[(size_t)Mc * NQKV];            // [B,S,3,H,D] fp32
__device__ float g_att[(size_t)Mc * HDc];             // attention out fp32
__device__ __nv_bfloat16 g_xh[(size_t)Mc * Kg];
__device__ __nv_bfloat16 g_xl[(size_t)Mc * Kg];
__device__ __nv_bfloat16 g_wqkvTh[(size_t)NQKV * Kg]; // wqkv^T [N,K]
__device__ __nv_bfloat16 g_wqkvTl[(size_t)NQKV * Kg];
__device__ __nv_bfloat16 g_woTh[(size_t)HDc * Kg];
__device__ __nv_bfloat16 g_woTl[(size_t)HDc * Kg];
__device__ __nv_bfloat16 g_atth[(size_t)Mc * Kg];
__device__ __nv_bfloat16 g_attl[(size_t)Mc * Kg];

// ---------------- PTX helpers ----------------------------------------------
__device__ __forceinline__ uint32_t smem_u32(const void* p) {
    uint32_t a;
    asm("{ .reg .u64 t; cvta.to.shared.u64 t, %1; cvt.u32.u64 %0, t; }"
        : "=r"(a) : "l"(p));
    return a;
}
#define CP_ASYNC16(dst, src) \
    asm volatile("cp.async.cg.shared.global [%0], [%1], 16;" :: "r"(dst), "l"(src))
#define CP_COMMIT() asm volatile("cp.async.commit_group;" ::: "memory")

__device__ __forceinline__ void ldsm4(uint32_t& r0, uint32_t& r1, uint32_t& r2,
                                      uint32_t& r3, uint32_t addr) {
    asm volatile("ldmatrix.sync.aligned.m8n8.x4.shared.b16 {%0,%1,%2,%3}, [%4];"
                 : "=r"(r0), "=r"(r1), "=r"(r2), "=r"(r3) : "r"(addr));
}
__device__ __forceinline__ void mma_bf16(float* d, const uint32_t* a,
                                         const uint32_t* b) {
    asm volatile(
        "mma.sync.aligned.m16n8k16.row.col.f32.bf16.bf16.f32 "
        "{%0,%1,%2,%3}, {%4,%5,%6,%7}, {%8,%9}, {%0,%1,%2,%3};"
        : "+f"(d[0]), "+f"(d[1]), "+f"(d[2]), "+f"(d[3])
        : "r"(a[0]), "r"(a[1]), "r"(a[2]), "r"(a[3]), "r"(b[0]), "r"(b[1]));
}

// ---------------- split kernels --------------------------------------------
__global__ __launch_bounds__(256) void split_kernel(
    const float* __restrict__ a, __nv_bfloat16* __restrict__ hi,
    __nv_bfloat16* __restrict__ lo)
{
    size_t i = ((size_t)blockIdx.x * 256 + threadIdx.x) * 4;
    float4 v = *(const float4*)(a + i);
    __nv_bfloat16 h0 = __float2bfloat16_rn(v.x);
    __nv_bfloat16 h1 = __float2bfloat16_rn(v.y);
    __nv_bfloat16 h2 = __float2bfloat16_rn(v.z);
    __nv_bfloat16 h3 = __float2bfloat16_rn(v.w);
    __nv_bfloat162* H = (__nv_bfloat162*)(hi + i);
    __nv_bfloat162* L = (__nv_bfloat162*)(lo + i);
    H[0] = __nv_bfloat162(h0, h1);
    H[1] = __nv_bfloat162(h2, h3);
    L[0] = __nv_bfloat162(__float2bfloat16_rn(v.x - __bfloat162float(h0)),
                          __float2bfloat16_rn(v.y - __bfloat162float(h1)));
    L[1] = __nv_bfloat162(__float2bfloat16_rn(v.z - __bfloat162float(h2)),
                          __float2bfloat16_rn(v.w - __bfloat162float(h3)));
}

// W[K,N] fp32 -> WT[N,K] bf16 hi/lo
__global__ __launch_bounds__(256) void transpose_split_kernel(
    const float* __restrict__ w, __nv_bfloat16* __restrict__ th,
    __nv_bfloat16* __restrict__ tl, int N)
{
    __shared__ float t[32][33];
    const int n0 = blockIdx.x * 32, k0 = blockIdx.y * 32;
    const int tx = threadIdx.x & 31, ty = threadIdx.x >> 5;
#pragma unroll
    for (int j = 0; j < 4; j++)
        t[ty + 8 * j][tx] = w[(size_t)(k0 + ty + 8 * j) * N + n0 + tx];
    __syncthreads();
#pragma unroll
    for (int j = 0; j < 4; j++) {
        float v = t[tx][ty + 8 * j];
        __nv_bfloat16 h = __float2bfloat16_rn(v);
        size_t o = (size_t)(n0 + ty + 8 * j) * Kg + k0 + tx;
        th[o] = h;
        tl[o] = __float2bfloat16_rn(v - __bfloat162float(h));
    }
}

// ---------------- mma.sync bf16 GEMM with 2-term split ----------------------
// C[M,N] = (Ah+Al)[M,K] @ (Bh+Bl)^T  with B given as [N,K] row-major.
// Block 128x128, BK=32, 256 threads (8 warps, 2x4), warp tile 64x32.
// SMEM rows padded to 40 bf16 (80B) -> conflict-free ldmatrix/cp.async.
#define BKq 32
#define STRIDEe 40                       // elements per padded row
#define TILE_B (128 * STRIDEe * 2)       // 10240 bytes per matrix tile
#define OFF_AH 0
#define OFF_AL TILE_B
#define OFF_BH (2 * TILE_B)
#define OFF_BL (3 * TILE_B)
#define STAGE_B (4 * TILE_B)             // 40960
#define GEMM_SMEM (2 * STAGE_B)          // 81920

__global__ __launch_bounds__(256) void gemm_mma_kernel(
    const __nv_bfloat16* __restrict__ Ah, const __nv_bfloat16* __restrict__ Al,
    const __nv_bfloat16* __restrict__ Bh, const __nv_bfloat16* __restrict__ Bl,
    float* __restrict__ C, int Nglob)
{
    extern __shared__ char sm[];
    const uint32_t smb = smem_u32(sm);

    const int tid = threadIdx.x;
    const int wid = tid >> 5, lid = tid & 31;
    const int wm = wid >> 2, wn = wid & 3;     // 2 x 4 warp grid
    const int m0 = blockIdx.y * 128;
    const int col0 = blockIdx.x * 128;

    float acc[4][4][4];
#pragma unroll
    for (int i = 0; i < 4; i++)
#pragma unroll
        for (int j = 0; j < 4; j++)
#pragma unroll
            for (int r = 0; r < 4; r++) acc[i][j][r] = 0.f;

    // stage loader: 512 16B-chunks per matrix (128 rows x 4 chunks)
    auto load_stage = [&](int s, int k0) {
        const uint32_t sb = smb + s * STAGE_B;
#pragma unroll
        for (int i = 0; i < 2; i++) {
            int c = tid + (i << 8);
            int row = c >> 2, kg = c & 3;
            uint32_t so = row * 80 + kg * 16;
            size_t ga = (size_t)(m0 + row) * Kg + k0 + (kg << 3);
            size_t gb = (size_t)(col0 + row) * Kg + k0 + (kg << 3);
            CP_ASYNC16(sb + OFF_AH + so, Ah + ga);
            CP_ASYNC16(sb + OFF_AL + so, Al + ga);
            CP_ASYNC16(sb + OFF_BH + so, Bh + gb);
            CP_ASYNC16(sb + OFF_BL + so, Bl + gb);
        }
    };

    const int nc = Kg / BKq;  // 32
    load_stage(0, 0);
    CP_COMMIT();

    // precomputed ldmatrix lane offsets (elements)
    const int a_lrow = lid & 15, a_lk = (lid >> 4) << 3;
    const int b_mat = lid >> 3, b_r = lid & 7;
    const int b_lrow = b_r + ((b_mat >> 1) << 3);   // n within 16-row group
    const int b_lk = (b_mat & 1) << 3;

    for (int c = 0; c < nc; c++) {
        const int s = c & 1;
        if (c + 1 < nc) {
            load_stage(s ^ 1, (c + 1) * BKq);
            CP_COMMIT();
            asm volatile("cp.async.wait_group 1;" ::: "memory");
        } else {
            asm volatile("cp.async.wait_group 0;" ::: "memory");
        }
        __syncthreads();

        const uint32_t sb = smb + s * STAGE_B;
#pragma unroll
        for (int ks = 0; ks < 2; ks++) {
            uint32_t ah[4][4], al[4][4], bh[2][4], bl[2][4];
#pragma unroll
            for (int i = 0; i < 4; i++) {
                uint32_t off =
                    ((wm * 64 + i * 16 + a_lrow) * STRIDEe + ks * 16 + a_lk) * 2;
                ldsm4(ah[i][0], ah[i][1], ah[i][2], ah[i][3], sb + OFF_AH + off);
                ldsm4(al[i][0], al[i][1], al[i][2], al[i][3], sb + OFF_AL + off);
            }
#pragma unroll
            for (int nb = 0; nb < 2; nb++) {
                uint32_t off =
                    ((wn * 32 + nb * 16 + b_lrow) * STRIDEe + ks * 16 + b_lk) * 2;
                ldsm4(bh[nb][0], bh[nb][1], bh[nb][2], bh[nb][3], sb + OFF_BH + off);
                ldsm4(bl[nb][0], bl[nb][1], bl[nb][2], bl[nb][3], sb + OFF_BL + off);
            }
#pragma unroll
            for (int i = 0; i < 4; i++)
#pragma unroll
                for (int j = 0; j < 4; j++) {
                    const uint32_t* ph = &bh[j >> 1][(j & 1) << 1];
                    const uint32_t* pl = &bl[j >> 1][(j & 1) << 1];
                    mma_bf16(acc[i][j], ah[i], ph);
                    mma_bf16(acc[i][j], ah[i], pl);
                    mma_bf16(acc[i][j], al[i], ph);
                }
        }
        __syncthreads();
    }

    // epilogue: fragment -> global (float2 stores)
#pragma unroll
    for (int i = 0; i < 4; i++) {
        const int row = m0 + wm * 64 + i * 16 + (lid >> 2);
#pragma unroll
        for (int j = 0; j < 4; j++) {
            const int col = col0 + wn * 32 + j * 8 + ((lid & 3) << 1);
            *(float2*)(C + (size_t)row * Nglob + col) =
                make_float2(acc[i][j][0], acc[i][j][1]);
            *(float2*)(C + (size_t)(row + 8) * Nglob + col) =
                make_float2(acc[i][j][2], acc[i][j][3]);
        }
    }
}

// ---------------- RoPE ------------------------------------------------------
__global__ __launch_bounds__(256) void rope_kernel(float* __restrict__ qkv)
{
    const size_t idx = (size_t)blockIdx.x * blockDim.x + threadIdx.x;
    const int i    = (int)(idx & 31);
    const int h    = (int)((idx >> 5) & 15);
    const int part = (int)((idx >> 9) & 1);
    const int s    = (int)((idx >> 10) & 2047);
    const int b    = (int)(idx >> 21);

    const double inv_freq = pow(10000.0, -2.0 * (double)i / 64.0);
    const float ang = (float)((double)s * inv_freq);
    float sn, cs;
    sincosf(ang, &sn, &cs);

    const size_t base = ((size_t)(b * Sc + s) * 3 + part) * (size_t)HDc + h * Dc;
    const float t1 = qkv[base + i];
    const float t2 = qkv[base + i + 32];
    qkv[base + i]      = t1 * cs - t2 * sn;
    qkv[base + i + 32] = t2 * cs + t1 * sn;
}

// ---------------- flash attention (fp32 SIMT, known-correct) ----------------
#define SWZ(row, grp) ((((grp) ^ ((row) >> 2)) & 15) << 2)

__global__ __launch_bounds__(256) void attn_kernel(
    const float* __restrict__ qkv, float* __restrict__ o_out)
{
    extern __shared__ float smf[];
    float* Qs = smf;
    float* Ks = smf + 64 * 64;
    float* Vs = smf + 2 * 64 * 64;
    float* Ps = smf + 3 * 64 * 64;

    const int tid = threadIdx.x;
    const int bh  = blockIdx.y;
    const int b   = bh >> 4;
    const int h   = bh & 15;
    const int q0  = blockIdx.x * 64;
    const int tq  = tid >> 4;
    const int tk  = tid & 15;

    const size_t rs = (size_t)NQKV;
    const float* qbase = qkv + (size_t)(b * Sc) * rs + h * Dc;
    const float* kbase = qbase + HDc;
    const float* vbase = qbase + 2 * HDc;

#pragma unroll
    for (int it = 0; it < 4; it++) {
        int idx = tid + it * 256;
        int qi  = idx >> 4;
        int d4  = (idx & 15) << 2;
        float4 v = *(const float4*)(qbase + (size_t)(q0 + qi) * rs + d4);
        int grp = qi >> 2, w = qi & 3;
        Qs[(d4 + 0) * 64 + SWZ(d4 + 0, grp) + w] = v.x;
        Qs[(d4 + 1) * 64 + SWZ(d4 + 1, grp) + w] = v.y;
        Qs[(d4 + 2) * 64 + SWZ(d4 + 2, grp) + w] = v.z;
        Qs[(d4 + 3) * 64 + SWZ(d4 + 3, grp) + w] = v.w;
    }

    float acc_o[4][4];
    float m_i[4], l_i[4];
#pragma unroll
    for (int i = 0; i < 4; i++) {
        m_i[i] = -1e30f;
        l_i[i] = 0.f;
#pragma unroll
        for (int j = 0; j < 4; j++) acc_o[i][j] = 0.f;
    }

    for (int kt = 0; kt < Sc / 64; kt++) {
        __syncthreads();
        const int k0 = kt * 64;
#pragma unroll
        for (int it = 0; it < 4; it++) {
            int idx = tid + it * 256;
            int ki  = idx >> 4;
            int d4  = (idx & 15) << 2;
            float4 kv = *(const float4*)(kbase + (size_t)(k0 + ki) * rs + d4);
            int grp = ki >> 2, w = ki & 3;
            Ks[(d4 + 0) * 64 + SWZ(d4 + 0, grp) + w] = kv.x;
            Ks[(d4 + 1) * 64 + SWZ(d4 + 1, grp) + w] = kv.y;
            Ks[(d4 + 2) * 64 + SWZ(d4 + 2, grp) + w] = kv.z;
            Ks[(d4 + 3) * 64 + SWZ(d4 + 3, grp) + w] = kv.w;
            float4 vv = *(const float4*)(vbase + (size_t)(k0 + ki) * rs + d4);
            *(float4*)&Vs[ki * 64 + d4] = vv;
        }
        __syncthreads();

        float acc_s[4][4];
#pragma unroll
        for (int i = 0; i < 4; i++)
#pragma unroll
            for (int j = 0; j < 4; j++) acc_s[i][j] = 0.f;

#pragma unroll 8
        for (int d = 0; d < 64; d++) {
            float a[4], bb[4];
            *(float4*)a  = *(const float4*)&Qs[d * 64 + SWZ(d, tq)];
            *(float4*)bb = *(const float4*)&Ks[d * 64 + SWZ(d, tk)];
#pragma unroll
            for (int i = 0; i < 4; i++)
#pragma unroll
                for (int j = 0; j < 4; j++)
                    acc_s[i][j] = fmaf(a[i], bb[j], acc_s[i][j]);
        }

#pragma unroll
        for (int i = 0; i < 4; i++) {
            float mx = -1e30f;
#pragma unroll
            for (int j = 0; j < 4; j++) {
                acc_s[i][j] *= 0.125f;
                mx = fmaxf(mx, acc_s[i][j]);
            }
#pragma unroll
            for (int off = 8; off; off >>= 1)
                mx = fmaxf(mx, __shfl_xor_sync(0xFFFFFFFFu, mx, off));
            const float m_new = fmaxf(m_i[i], mx);
            const float f = expf(m_i[i] - m_new);
            float sum = 0.f;
#pragma unroll
            for (int j = 0; j < 4; j++) {
                float p = expf(acc_s[i][j] - m_new);
                Ps[(tk * 4 + j) * 64 + ((tq ^ tk) << 2) + i] = p;
                sum += p;
            }
#pragma unroll
            for (int off = 8; off; off >>= 1)
                sum += __shfl_xor_sync(0xFFFFFFFFu, sum, off);
            l_i[i] = l_i[i] * f + sum;
            m_i[i] = m_new;
#pragma unroll
            for (int j = 0; j < 4; j++) acc_o[i][j] *= f;
        }
        __syncthreads();

#pragma unroll 8
        for (int ki = 0; ki < 64; ki++) {
            float a[4], bb[4];
            *(float4*)a  = *(const float4*)&Ps[ki * 64 + SWZ(ki, tq)];
            *(float4*)bb = *(const float4*)&Vs[ki * 64 + tk * 4];
#pragma unroll
            for (int i = 0; i < 4; i++)
#pragma unroll
                for (int j = 0; j < 4; j++)
                    acc_o[i][j] = fmaf(a[i], bb[j], acc_o[i][j]);
        }
    }

#pragma unroll
    for (int i = 0; i < 4; i++) {
        const float inv = 1.f / l_i[i];
        float4 v = make_float4(acc_o[i][0] * inv, acc_o[i][1] * inv,
                               acc_o[i][2] * inv, acc_o[i][3] * inv);
        *(float4*)(o_out + (size_t)(b * Sc + q0 + tq * 4 + i) * HDc + h * Dc + tk * 4) = v;
    }
}

// ---------------------------------------------------------------------------
extern "C" void kernel_launch(void* const* d_in, const int* in_sizes, int n_in,
                              void* d_out, int out_size)
{
    const float* x    = (const float*)d_in[0];
    const float* wqkv = (const float*)d_in[1];
    const float* wo   = (const float*)d_in[2];
    float* out = (float*)d_out;

    float *qkv = nullptr, *att = nullptr;
    __nv_bfloat16 *xh, *xl, *wqh, *wql, *woh, *wol, *ath, *atl;
    cudaGetSymbolAddress((void**)&qkv, g_qkv);
    cudaGetSymbolAddress((void**)&att, g_att);
    cudaGetSymbolAddress((void**)&xh, g_xh);
    cudaGetSymbolAddress((void**)&xl, g_xl);
    cudaGetSymbolAddress((void**)&wqh, g_wqkvTh);
    cudaGetSymbolAddress((void**)&wql, g_wqkvTl);
    cudaGetSymbolAddress((void**)&woh, g_woTh);
    cudaGetSymbolAddress((void**)&wol, g_woTl);
    cudaGetSymbolAddress((void**)&ath, g_atth);
    cudaGetSymbolAddress((void**)&atl, g_attl);

    static bool attr_set = false;
    if (!attr_set) {
        cudaFuncSetAttribute(gemm_mma_kernel,
                             cudaFuncAttributeMaxDynamicSharedMemorySize, GEMM_SMEM);
        cudaFuncSetAttribute(attn_kernel,
                             cudaFuncAttributeMaxDynamicSharedMemorySize, 65536);
        attr_set = true;
    }

    // 1) split x; transpose+split wqkv
    split_kernel<<<(Mc * Kg) / 1024, 256>>>(x, xh, xl);
    transpose_split_kernel<<<dim3(NQKV / 32, Kg / 32), 256>>>(wqkv, wqh, wql, NQKV);

    // 2) qkv = x @ wqkv (tensor cores, bf16 split)
    gemm_mma_kernel<<<dim3(NQKV / 128, Mc / 128), 256, GEMM_SMEM>>>(
        xh, xl, wqh, wql, qkv, NQKV);

    // 3) RoPE in-place
    rope_kernel<<<(Bc * Sc * 2 * Hc * (Dc / 2)) / 256, 256>>>(qkv);

    // 4) flash attention -> att
    attn_kernel<<<dim3(Sc / 64, Bc * Hc), 256, 65536>>>(qkv, att);

    // 5) split att; transpose+split wo
    split_kernel<<<(Mc * Kg) / 1024, 256>>>(att, ath, atl);
    transpose_split_kernel<<<dim3(HDc / 32, Kg / 32), 256>>>(wo, woh, wol, HDc);

    // 6) out = att @ wo
    gemm_mma_kernel<<<dim3(HDc / 128, Mc / 128), 256, GEMM_SMEM>>>(
        ath, atl, woh, wol, out, HDc);
}

// round 5
// speedup vs baseline: 2.7752x; 2.0786x over previous
#include <cuda_runtime.h>
#include <cuda_bf16.h>
#include <math.h>
#include <stdint.h>

#define Bc 4
#define Sc 2048
#define HDc 1024
#define Hc 16
#define Dc 64
#define Mc (Bc * Sc)          // 8192 rows
#define NQKV (3 * HDc)        // 3072
#define Kg 1024               // K dim of both GEMMs

// ---------------- scratch (__device__ globals; no allocs allowed) ----------
__device__ float g_qkv[(size_t)Mc * NQKV];            // [B,S,3,H,D] fp32
__device__ __nv_bfloat16 g_xh[(size_t)Mc * Kg];
__device__ __nv_bfloat16 g_xl[(size_t)Mc * Kg];
__device__ __nv_bfloat16 g_wqkvTh[(size_t)NQKV * Kg]; // wqkv^T [N,K]
__device__ __nv_bfloat16 g_wqkvTl[(size_t)NQKV * Kg];
__device__ __nv_bfloat16 g_woTh[(size_t)HDc * Kg];
__device__ __nv_bfloat16 g_woTl[(size_t)HDc * Kg];
__device__ __nv_bfloat16 g_atth[(size_t)Mc * Kg];     // attention out hi (A of wo gemm)
__device__ __nv_bfloat16 g_attl[(size_t)Mc * Kg];     // attention out lo
// head-major bf16 hi/lo Q/K/V: [bh=64][s=2048][d=64]
#define HM_ELEMS ((size_t)64 * Sc * Dc)
__device__ __nv_bfloat16 g_qh[HM_ELEMS], g_ql[HM_ELEMS];
__device__ __nv_bfloat16 g_kh[HM_ELEMS], g_kl[HM_ELEMS];
__device__ __nv_bfloat16 g_vh[HM_ELEMS], g_vl[HM_ELEMS];

// ---------------- PTX helpers ----------------------------------------------
__device__ __forceinline__ uint32_t smem_u32(const void* p) {
    uint32_t a;
    asm("{ .reg .u64 t; cvta.to.shared.u64 t, %1; cvt.u32.u64 %0, t; }"
        : "=r"(a) : "l"(p));
    return a;
}
#define CP_ASYNC16(dst, src) \
    asm volatile("cp.async.cg.shared.global [%0], [%1], 16;" :: "r"(dst), "l"(src))
#define CP_COMMIT() asm volatile("cp.async.commit_group;" ::: "memory")

__device__ __forceinline__ void ldsm4(uint32_t& r0, uint32_t& r1, uint32_t& r2,
                                      uint32_t& r3, uint32_t addr) {
    asm volatile("ldmatrix.sync.aligned.m8n8.x4.shared.b16 {%0,%1,%2,%3}, [%4];"
                 : "=r"(r0), "=r"(r1), "=r"(r2), "=r"(r3) : "r"(addr));
}
__device__ __forceinline__ void ldsm4t(uint32_t& r0, uint32_t& r1, uint32_t& r2,
                                       uint32_t& r3, uint32_t addr) {
    asm volatile("ldmatrix.sync.aligned.m8n8.x4.trans.shared.b16 {%0,%1,%2,%3}, [%4];"
                 : "=r"(r0), "=r"(r1), "=r"(r2), "=r"(r3) : "r"(addr));
}
__device__ __forceinline__ void mma_bf16(float* d, const uint32_t* a,
                                         const uint32_t* b) {
    asm volatile(
        "mma.sync.aligned.m16n8k16.row.col.f32.bf16.bf16.f32 "
        "{%0,%1,%2,%3}, {%4,%5,%6,%7}, {%8,%9}, {%0,%1,%2,%3};"
        : "+f"(d[0]), "+f"(d[1]), "+f"(d[2]), "+f"(d[3])
        : "r"(a[0]), "r"(a[1]), "r"(a[2]), "r"(a[3]), "r"(b[0]), "r"(b[1]));
}
__device__ __forceinline__ uint32_t pack_hi(float a, float b) {
    __nv_bfloat162 t(__float2bfloat16_rn(a), __float2bfloat16_rn(b));
    return *(uint32_t*)&t;
}
__device__ __forceinline__ uint32_t pack_lo(float a, float b) {
    float ra = a - __bfloat162float(__float2bfloat16_rn(a));
    float rb = b - __bfloat162float(__float2bfloat16_rn(b));
    __nv_bfloat162 t(__float2bfloat16_rn(ra), __float2bfloat16_rn(rb));
    return *(uint32_t*)&t;
}

// ---------------- split kernels --------------------------------------------
__global__ __launch_bounds__(256) void split_kernel(
    const float* __restrict__ a, __nv_bfloat16* __restrict__ hi,
    __nv_bfloat16* __restrict__ lo)
{
    size_t i = ((size_t)blockIdx.x * 256 + threadIdx.x) * 4;
    float4 v = *(const float4*)(a + i);
    __nv_bfloat16 h0 = __float2bfloat16_rn(v.x);
    __nv_bfloat16 h1 = __float2bfloat16_rn(v.y);
    __nv_bfloat16 h2 = __float2bfloat16_rn(v.z);
    __nv_bfloat16 h3 = __float2bfloat16_rn(v.w);
    __nv_bfloat162* H = (__nv_bfloat162*)(hi + i);
    __nv_bfloat162* L = (__nv_bfloat162*)(lo + i);
    H[0] = __nv_bfloat162(h0, h1);
    H[1] = __nv_bfloat162(h2, h3);
    L[0] = __nv_bfloat162(__float2bfloat16_rn(v.x - __bfloat162float(h0)),
                          __float2bfloat16_rn(v.y - __bfloat162float(h1)));
    L[1] = __nv_bfloat162(__float2bfloat16_rn(v.z - __bfloat162float(h2)),
                          __float2bfloat16_rn(v.w - __bfloat162float(h3)));
}

__global__ __launch_bounds__(256) void transpose_split_kernel(
    const float* __restrict__ w, __nv_bfloat16* __restrict__ th,
    __nv_bfloat16* __restrict__ tl, int N)
{
    __shared__ float t[32][33];
    const int n0 = blockIdx.x * 32, k0 = blockIdx.y * 32;
    const int tx = threadIdx.x & 31, ty = threadIdx.x >> 5;
#pragma unroll
    for (int j = 0; j < 4; j++)
        t[ty + 8 * j][tx] = w[(size_t)(k0 + ty + 8 * j) * N + n0 + tx];
    __syncthreads();
#pragma unroll
    for (int j = 0; j < 4; j++) {
        float v = t[tx][ty + 8 * j];
        __nv_bfloat16 h = __float2bfloat16_rn(v);
        size_t o = (size_t)(n0 + ty + 8 * j) * Kg + k0 + tx;
        th[o] = h;
        tl[o] = __float2bfloat16_rn(v - __bfloat162float(h));
    }
}

// ---------------- mma.sync bf16 GEMM with 2-term split (unchanged) ----------
#define BKq 32
#define STRIDEe 40
#define TILE_B (128 * STRIDEe * 2)
#define OFF_AH 0
#define OFF_AL TILE_B
#define OFF_BH (2 * TILE_B)
#define OFF_BL (3 * TILE_B)
#define STAGE_B (4 * TILE_B)
#define GEMM_SMEM (2 * STAGE_B)

__global__ __launch_bounds__(256) void gemm_mma_kernel(
    const __nv_bfloat16* __restrict__ Ah, const __nv_bfloat16* __restrict__ Al,
    const __nv_bfloat16* __restrict__ Bh, const __nv_bfloat16* __restrict__ Bl,
    float* __restrict__ C, int Nglob)
{
    extern __shared__ char sm[];
    const uint32_t smb = smem_u32(sm);

    const int tid = threadIdx.x;
    const int wid = tid >> 5, lid = tid & 31;
    const int wm = wid >> 2, wn = wid & 3;
    const int m0 = blockIdx.y * 128;
    const int col0 = blockIdx.x * 128;

    float acc[4][4][4];
#pragma unroll
    for (int i = 0; i < 4; i++)
#pragma unroll
        for (int j = 0; j < 4; j++)
#pragma unroll
            for (int r = 0; r < 4; r++) acc[i][j][r] = 0.f;

    auto load_stage = [&](int s, int k0) {
        const uint32_t sb = smb + s * STAGE_B;
#pragma unroll
        for (int i = 0; i < 2; i++) {
            int c = tid + (i << 8);
            int row = c >> 2, kg = c & 3;
            uint32_t so = row * 80 + kg * 16;
            size_t ga = (size_t)(m0 + row) * Kg + k0 + (kg << 3);
            size_t gb = (size_t)(col0 + row) * Kg + k0 + (kg << 3);
            CP_ASYNC16(sb + OFF_AH + so, Ah + ga);
            CP_ASYNC16(sb + OFF_AL + so, Al + ga);
            CP_ASYNC16(sb + OFF_BH + so, Bh + gb);
            CP_ASYNC16(sb + OFF_BL + so, Bl + gb);
        }
    };

    const int nc = Kg / BKq;
    load_stage(0, 0);
    CP_COMMIT();

    const int a_lrow = lid & 15, a_lk = (lid >> 4) << 3;
    const int b_mat = lid >> 3, b_r = lid & 7;
    const int b_lrow = b_r + ((b_mat >> 1) << 3);
    const int b_lk = (b_mat & 1) << 3;

    for (int c = 0; c < nc; c++) {
        const int s = c & 1;
        if (c + 1 < nc) {
            load_stage(s ^ 1, (c + 1) * BKq);
            CP_COMMIT();
            asm volatile("cp.async.wait_group 1;" ::: "memory");
        } else {
            asm volatile("cp.async.wait_group 0;" ::: "memory");
        }
        __syncthreads();

        const uint32_t sb = smb + s * STAGE_B;
#pragma unroll
        for (int ks = 0; ks < 2; ks++) {
            uint32_t ah[4][4], al[4][4], bh[2][4], bl[2][4];
#pragma unroll
            for (int i = 0; i < 4; i++) {
                uint32_t off =
                    ((wm * 64 + i * 16 + a_lrow) * STRIDEe + ks * 16 + a_lk) * 2;
                ldsm4(ah[i][0], ah[i][1], ah[i][2], ah[i][3], sb + OFF_AH + off);
                ldsm4(al[i][0], al[i][1], al[i][2], al[i][3], sb + OFF_AL + off);
            }
#pragma unroll
            for (int nb = 0; nb < 2; nb++) {
                uint32_t off =
                    ((wn * 32 + nb * 16 + b_lrow) * STRIDEe + ks * 16 + b_lk) * 2;
                ldsm4(bh[nb][0], bh[nb][1], bh[nb][2], bh[nb][3], sb + OFF_BH + off);
                ldsm4(bl[nb][0], bl[nb][1], bl[nb][2], bl[nb][3], sb + OFF_BL + off);
            }
#pragma unroll
            for (int i = 0; i < 4; i++)
#pragma unroll
                for (int j = 0; j < 4; j++) {
                    const uint32_t* ph = &bh[j >> 1][(j & 1) << 1];
                    const uint32_t* pl = &bl[j >> 1][(j & 1) << 1];
                    mma_bf16(acc[i][j], ah[i], ph);
                    mma_bf16(acc[i][j], ah[i], pl);
                    mma_bf16(acc[i][j], al[i], ph);
                }
        }
        __syncthreads();
    }

#pragma unroll
    for (int i = 0; i < 4; i++) {
        const int row = m0 + wm * 64 + i * 16 + (lid >> 2);
#pragma unroll
        for (int j = 0; j < 4; j++) {
            const int col = col0 + wn * 32 + j * 8 + ((lid & 3) << 1);
            *(float2*)(C + (size_t)row * Nglob + col) =
                make_float2(acc[i][j][0], acc[i][j][1]);
            *(float2*)(C + (size_t)(row + 8) * Nglob + col) =
                make_float2(acc[i][j][2], acc[i][j][3]);
        }
    }
}

// ---------------- RoPE + head-major bf16 repack ----------------------------
__global__ __launch_bounds__(256) void repack_kernel(const float* __restrict__ qkv)
{
    const size_t idx = (size_t)blockIdx.x * blockDim.x + threadIdx.x;
    const int i = (int)(idx & 31);
    const int h = (int)((idx >> 5) & 15);
    const int s = (int)((idx >> 9) & 2047);
    const int b = (int)(idx >> 20);

    const double inv_freq = pow(10000.0, -2.0 * (double)i / 64.0);
    const float ang = (float)((double)s * inv_freq);
    float sn, cs;
    sincosf(ang, &sn, &cs);

    const size_t ibase = ((size_t)(b * Sc + s) * 3) * (size_t)HDc + h * Dc;
    const size_t obase = ((size_t)(b * Hc + h) * Sc + s) * (size_t)Dc;

    // Q (rope + 0.125 scale, exact power-of-two fold)
    {
        float t1 = qkv[ibase + i], t2 = qkv[ibase + i + 32];
        float r1 = (t1 * cs - t2 * sn) * 0.125f;
        float r2 = (t2 * cs + t1 * sn) * 0.125f;
        __nv_bfloat16 h1 = __float2bfloat16_rn(r1), h2 = __float2bfloat16_rn(r2);
        g_qh[obase + i] = h1;
        g_qh[obase + i + 32] = h2;
        g_ql[obase + i] = __float2bfloat16_rn(r1 - __bfloat162float(h1));
        g_ql[obase + i + 32] = __float2bfloat16_rn(r2 - __bfloat162float(h2));
    }
    // K (rope)
    {
        float t1 = qkv[ibase + HDc + i], t2 = qkv[ibase + HDc + i + 32];
        float r1 = t1 * cs - t2 * sn;
        float r2 = t2 * cs + t1 * sn;
        __nv_bfloat16 h1 = __float2bfloat16_rn(r1), h2 = __float2bfloat16_rn(r2);
        g_kh[obase + i] = h1;
        g_kh[obase + i + 32] = h2;
        g_kl[obase + i] = __float2bfloat16_rn(r1 - __bfloat162float(h1));
        g_kl[obase + i + 32] = __float2bfloat16_rn(r2 - __bfloat162float(h2));
    }
    // V (straight)
    {
        float t1 = qkv[ibase + 2 * HDc + i], t2 = qkv[ibase + 2 * HDc + i + 32];
        __nv_bfloat16 h1 = __float2bfloat16_rn(t1), h2 = __float2bfloat16_rn(t2);
        g_vh[obase + i] = h1;
        g_vh[obase + i + 32] = h2;
        g_vl[obase + i] = __float2bfloat16_rn(t1 - __bfloat162float(h1));
        g_vl[obase + i + 32] = __float2bfloat16_rn(t2 - __bfloat162float(h2));
    }
}

// ---------------- flash attention via mma.sync bf16 split -------------------
// Block: 128 queries x one (b,h). 8 warps, warp w owns rows 16w..16w+15.
// KV tiles of 128. Scores/PV: 3-term bf16 split, fp32 accum.
// FIXED: stage loaders now fill the full 128B row (8 x 16B chunks).
#define AS 72                        // padded smem row stride (elements)
#define ATILE (128 * AS * 2)         // 18432 B per matrix tile
#define ATT_SMEM (4 * ATILE)         // 73728

__global__ __launch_bounds__(256) void attn_mma_kernel(
    __nv_bfloat16* __restrict__ Oh, __nv_bfloat16* __restrict__ Ol)
{
    extern __shared__ char sm[];
    const uint32_t s_kh = smem_u32(sm);
    const uint32_t s_kl = s_kh + ATILE;
    const uint32_t s_vh = s_kh + 2 * ATILE;
    const uint32_t s_vl = s_kh + 3 * ATILE;

    const int tid = threadIdx.x, wid = tid >> 5, lid = tid & 31;
    const int bh = blockIdx.y;
    const int q0 = blockIdx.x * 128;
    const size_t hoff = (size_t)bh * Sc * Dc;

    const int a_lrow = lid & 15, a_lk = (lid >> 4) << 3;
    const int b_lrow = (lid & 7) + ((lid >> 4) << 3);
    const int b_lk = ((lid >> 3) & 1) << 3;
    const int v_krow = (lid & 7) + (((lid >> 3) & 1) << 3);
    const int v_dcol = (lid >> 4) << 3;

    // ---- stage Q tile into s_kh/s_kl (full 128B rows), pull A-frags ----
#pragma unroll
    for (int i = 0; i < 4; i++) {
        int c = tid + (i << 8);         // 0..1023
        int row = c >> 3, ch = c & 7;   // 128 rows x 8 chunks
        uint32_t so = row * (AS * 2) + ch * 16;
        size_t g = hoff + (size_t)(q0 + row) * Dc + ch * 8;
        CP_ASYNC16(s_kh + so, g_qh + g);
        CP_ASYNC16(s_kl + so, g_ql + g);
    }
    CP_COMMIT();
    asm volatile("cp.async.wait_group 0;" ::: "memory");
    __syncthreads();

    uint32_t qh[4][4], ql[4][4];
#pragma unroll
    for (int kc = 0; kc < 4; kc++) {
        uint32_t off = (wid * 16 + a_lrow) * (AS * 2) + (kc * 16 + a_lk) * 2;
        ldsm4(qh[kc][0], qh[kc][1], qh[kc][2], qh[kc][3], s_kh + off);
        ldsm4(ql[kc][0], ql[kc][1], ql[kc][2], ql[kc][3], s_kl + off);
    }
    __syncthreads();

    float acc_o[8][4];
#pragma unroll
    for (int n = 0; n < 8; n++)
#pragma unroll
        for (int r = 0; r < 4; r++) acc_o[n][r] = 0.f;
    float m0 = -1e30f, m1 = -1e30f, l0 = 0.f, l1 = 0.f;

    for (int kt = 0; kt < Sc / 128; kt++) {
        const int k0 = kt * 128;
        // load K/V hi/lo tiles (full 128B rows)
#pragma unroll
        for (int i = 0; i < 4; i++) {
            int c = tid + (i << 8);
            int row = c >> 3, ch = c & 7;
            uint32_t so = row * (AS * 2) + ch * 16;
            size_t g = hoff + (size_t)(k0 + row) * Dc + ch * 8;
            CP_ASYNC16(s_kh + so, g_kh + g);
            CP_ASYNC16(s_kl + so, g_kl + g);
            CP_ASYNC16(s_vh + so, g_vh + g);
            CP_ASYNC16(s_vl + so, g_vl + g);
        }
        CP_COMMIT();
        asm volatile("cp.async.wait_group 0;" ::: "memory");
        __syncthreads();

        // ---- scores ----
        float ps[16][4];
#pragma unroll
        for (int n = 0; n < 16; n++)
#pragma unroll
            for (int r = 0; r < 4; r++) ps[n][r] = 0.f;

#pragma unroll
        for (int ng = 0; ng < 8; ng++) {
#pragma unroll
            for (int kc = 0; kc < 4; kc++) {
                uint32_t off =
                    (ng * 16 + b_lrow) * (AS * 2) + (kc * 16 + b_lk) * 2;
                uint32_t bh4[4], bl4[4];
                ldsm4(bh4[0], bh4[1], bh4[2], bh4[3], s_kh + off);
                ldsm4(bl4[0], bl4[1], bl4[2], bl4[3], s_kl + off);
#pragma unroll
                for (int j = 0; j < 2; j++) {
                    mma_bf16(ps[2 * ng + j], qh[kc], &bh4[2 * j]);
                    mma_bf16(ps[2 * ng + j], qh[kc], &bl4[2 * j]);
                    mma_bf16(ps[2 * ng + j], ql[kc], &bh4[2 * j]);
                }
            }
        }

        // ---- online softmax ----
        float mx0 = -1e30f, mx1 = -1e30f;
#pragma unroll
        for (int n = 0; n < 16; n++) {
            mx0 = fmaxf(mx0, fmaxf(ps[n][0], ps[n][1]));
            mx1 = fmaxf(mx1, fmaxf(ps[n][2], ps[n][3]));
        }
#pragma unroll
        for (int off = 1; off <= 2; off <<= 1) {
            mx0 = fmaxf(mx0, __shfl_xor_sync(0xFFFFFFFFu, mx0, off));
            mx1 = fmaxf(mx1, __shfl_xor_sync(0xFFFFFFFFu, mx1, off));
        }
        const float mn0 = fmaxf(m0, mx0), mn1 = fmaxf(m1, mx1);
        const float f0 = __expf(m0 - mn0), f1 = __expf(m1 - mn1);
        m0 = mn0; m1 = mn1;
        float sum0 = 0.f, sum1 = 0.f;
#pragma unroll
        for (int n = 0; n < 16; n++) {
            ps[n][0] = __expf(ps[n][0] - mn0);
            ps[n][1] = __expf(ps[n][1] - mn0);
            ps[n][2] = __expf(ps[n][2] - mn1);
            ps[n][3] = __expf(ps[n][3] - mn1);
            sum0 += ps[n][0] + ps[n][1];
            sum1 += ps[n][2] + ps[n][3];
        }
#pragma unroll
        for (int off = 1; off <= 2; off <<= 1) {
            sum0 += __shfl_xor_sync(0xFFFFFFFFu, sum0, off);
            sum1 += __shfl_xor_sync(0xFFFFFFFFu, sum1, off);
        }
        l0 = l0 * f0 + sum0;
        l1 = l1 * f1 + sum1;
#pragma unroll
        for (int n = 0; n < 8; n++) {
            acc_o[n][0] *= f0; acc_o[n][1] *= f0;
            acc_o[n][2] *= f1; acc_o[n][3] *= f1;
        }

        // ---- PV ----
#pragma unroll
        for (int kc = 0; kc < 8; kc++) {
            uint32_t a_h[4], a_l[4];
            a_h[0] = pack_hi(ps[2 * kc][0], ps[2 * kc][1]);
            a_h[1] = pack_hi(ps[2 * kc][2], ps[2 * kc][3]);
            a_h[2] = pack_hi(ps[2 * kc + 1][0], ps[2 * kc + 1][1]);
            a_h[3] = pack_hi(ps[2 * kc + 1][2], ps[2 * kc + 1][3]);
            a_l[0] = pack_lo(ps[2 * kc][0], ps[2 * kc][1]);
            a_l[1] = pack_lo(ps[2 * kc][2], ps[2 * kc][3]);
            a_l[2] = pack_lo(ps[2 * kc + 1][0], ps[2 * kc + 1][1]);
            a_l[3] = pack_lo(ps[2 * kc + 1][2], ps[2 * kc + 1][3]);
#pragma unroll
            for (int ng = 0; ng < 4; ng++) {
                uint32_t off = (kc * 16 + v_krow) * (AS * 2)
                             + (ng * 16 + v_dcol) * 2;
                uint32_t vh4[4], vl4[4];
                ldsm4t(vh4[0], vh4[1], vh4[2], vh4[3], s_vh + off);
                ldsm4t(vl4[0], vl4[1], vl4[2], vl4[3], s_vl + off);
#pragma unroll
                for (int j = 0; j < 2; j++) {
                    mma_bf16(acc_o[2 * ng + j], a_h, &vh4[2 * j]);
                    mma_bf16(acc_o[2 * ng + j], a_h, &vl4[2 * j]);
                    mma_bf16(acc_o[2 * ng + j], a_l, &vh4[2 * j]);
                }
            }
        }
        __syncthreads();
    }

    // ---- epilogue: normalize, split to bf16 hi/lo, store [B*S, 1024] ----
    const float inv0 = 1.f / l0, inv1 = 1.f / l1;
    const int b = bh >> 4, h = bh & 15;
    const int row_g0 = b * Sc + q0 + wid * 16 + (lid >> 2);
#pragma unroll
    for (int n = 0; n < 8; n++) {
        const int col = h * Dc + n * 8 + ((lid & 3) << 1);
        float v0 = acc_o[n][0] * inv0, v1 = acc_o[n][1] * inv0;
        float v2 = acc_o[n][2] * inv1, v3 = acc_o[n][3] * inv1;
        *(uint32_t*)(g_atth + (size_t)row_g0 * HDc + col) = pack_hi(v0, v1);
        *(uint32_t*)(g_attl + (size_t)row_g0 * HDc + col) = pack_lo(v0, v1);
        *(uint32_t*)(g_atth + (size_t)(row_g0 + 8) * HDc + col) = pack_hi(v2, v3);
        *(uint32_t*)(g_attl + (size_t)(row_g0 + 8) * HDc + col) = pack_lo(v2, v3);
    }
    (void)Oh; (void)Ol;
}

// ---------------------------------------------------------------------------
extern "C" void kernel_launch(void* const* d_in, const int* in_sizes, int n_in,
                              void* d_out, int out_size)
{
    const float* x    = (const float*)d_in[0];
    const float* wqkv = (const float*)d_in[1];
    const float* wo   = (const float*)d_in[2];
    float* out = (float*)d_out;

    float* qkv = nullptr;
    __nv_bfloat16 *xh, *xl, *wqh, *wql, *woh, *wol, *ath, *atl;
    cudaGetSymbolAddress((void**)&qkv, g_qkv);
    cudaGetSymbolAddress((void**)&xh, g_xh);
    cudaGetSymbolAddress((void**)&xl, g_xl);
    cudaGetSymbolAddress((void**)&wqh, g_wqkvTh);
    cudaGetSymbolAddress((void**)&wql, g_wqkvTl);
    cudaGetSymbolAddress((void**)&woh, g_woTh);
    cudaGetSymbolAddress((void**)&wol, g_woTl);
    cudaGetSymbolAddress((void**)&ath, g_atth);
    cudaGetSymbolAddress((void**)&atl, g_attl);

    static bool attr_set = false;
    if (!attr_set) {
        cudaFuncSetAttribute(gemm_mma_kernel,
                             cudaFuncAttributeMaxDynamicSharedMemorySize, GEMM_SMEM);
        cudaFuncSetAttribute(attn_mma_kernel,
                             cudaFuncAttributeMaxDynamicSharedMemorySize, ATT_SMEM);
        attr_set = true;
    }

    // 1) split x; transpose+split wqkv
    split_kernel<<<(Mc * Kg) / 1024, 256>>>(x, xh, xl);
    transpose_split_kernel<<<dim3(NQKV / 32, Kg / 32), 256>>>(wqkv, wqh, wql, NQKV);

    // 2) qkv = x @ wqkv (tensor cores)
    gemm_mma_kernel<<<dim3(NQKV / 128, Mc / 128), 256, GEMM_SMEM>>>(
        xh, xl, wqh, wql, qkv, NQKV);

    // 3) rope + repack to head-major bf16 hi/lo
    repack_kernel<<<(Bc * Sc * Hc * 32) / 256, 256>>>(qkv);

    // 4) flash attention (tensor cores) -> g_atth/g_attl directly
    attn_mma_kernel<<<dim3(Sc / 128, Bc * Hc), 256, ATT_SMEM>>>(ath, atl);

    // 5) transpose+split wo; out = att @ wo
    transpose_split_kernel<<<dim3(HDc / 32, Kg / 32), 256>>>(wo, woh, wol, HDc);
    gemm_mma_kernel<<<dim3(HDc / 128, Mc / 128), 256, GEMM_SMEM>>>(
        ath, atl, woh, wol, out, HDc);
}